// round 2
// baseline (speedup 1.0000x reference)
#include <cuda_runtime.h>

// CBFHalfspace collapses analytically:
//   h(x) = [1+x0, 1-x0, 1+x1, 1-x1];  Lfh = Lf2h = LgLfh = 0  (affine h, A cols sum to 0)
// Output row: [1+x0, 1-x0, 1+x1, 1-x1, 0,0,0,0]. f, g are dead inputs.
//
// R2: coalesced float4 staging of x through shared memory.
//   - Each block handles 1024 rows = 7168 floats = 1792 float4 (28 KB smem).
//   - Load phase: 7 fully-coalesced float4 loads/thread (minimal L1 wavefronts).
//   - Compute phase: x0/x1 read from shared; bank index 7*lane mod 32 is a
//     permutation (gcd(7,32)=1) -> conflict-free.
//   - Stores: two STG.128 per row, direct to gmem.

#define THREADS 256
#define ROWS_PER_BLOCK 1024                    // 256 threads * 4 rows
#define F4_PER_BLOCK (ROWS_PER_BLOCK * 7 / 4)  // 1792

__global__ void __launch_bounds__(THREADS)
cbf_kernel(const float4* __restrict__ x4, float4* __restrict__ out4, int n)
{
    __shared__ float4 buf[F4_PER_BLOCK];       // 28 KB

    const int tid  = threadIdx.x;
    const int lane = tid & 31;
    const int wid  = tid >> 5;

    const int rowBase = blockIdx.x * ROWS_PER_BLOCK;
    const long long f4Base = (long long)blockIdx.x * F4_PER_BLOCK;

    // How many rows this block actually owns (tail block may be partial).
    const int rowsHere = min(ROWS_PER_BLOCK, n - rowBase);
    const int f4Here   = (rowsHere * 7 + 3) / 4;   // float4 count covering those rows

    // Phase 1: coalesced float4 stage into shared.
    #pragma unroll
    for (int k = 0; k < 7; k++) {
        int idx = k * THREADS + tid;
        if (idx < f4Here) buf[idx] = x4[f4Base + idx];
    }
    __syncthreads();

    // Phase 2: compute + store. Warp w handles rows [w*128, w*128+128),
    // thread pattern lane + 32*j -> conflict-free smem reads.
    const float* bf = (const float*)buf;
    #pragma unroll
    for (int j = 0; j < 4; j++) {
        int row = wid * 128 + 32 * j + lane;   // 0..1023 within block
        if (row < rowsHere) {
            float x0 = bf[row * 7 + 0];
            float x1 = bf[row * 7 + 1];
            float4 h = make_float4(1.0f + x0, 1.0f - x0, 1.0f + x1, 1.0f - x1);
            long long g = rowBase + row;
            out4[2 * g + 0] = h;
            out4[2 * g + 1] = make_float4(0.0f, 0.0f, 0.0f, 0.0f);
        }
    }
}

extern "C" void kernel_launch(void* const* d_in, const int* in_sizes, int n_in,
                              void* d_out, int out_size)
{
    const float4* x4 = (const float4*)d_in[0];   // (B,7) fp32, B*7 divisible by 4 here
    float4* out4 = (float4*)d_out;               // (B,8) fp32 = 2 float4/row

    const int n = in_sizes[0] / 7;               // B rows
    const int blocks = (n + ROWS_PER_BLOCK - 1) / ROWS_PER_BLOCK;
    cbf_kernel<<<blocks, THREADS>>>(x4, out4, n);
}

// round 3
// speedup vs baseline: 1.1341x; 1.1341x over previous
#include <cuda_runtime.h>

// CBFHalfspace collapses analytically:
//   h(x) = [1+x0, 1-x0, 1+x1, 1-x1];  Lfh = Lf2h = 0, LgLfh = (0,0)  (affine h, A cols sum 0)
// Output row: [1+x0, 1-x0, 1+x1, 1-x1, 0,0,0,0]. f, g are dead inputs.
//
// R3: minimal-L1-wavefront design.
//   Loads : coalesced float4 stage of x into smem (7 lines / 32 rows = minimum).
//   Stores: threads mapped CONTIGUOUSLY onto the output float4 stream
//           (j odd -> zero quad, j even -> h quad of row j>>1), so every store
//           wavefront is a dense 512B write (8 lines / 32 rows = minimum).
//   Smem reads buf[7*row]: 16 consecutive rows * stride 7 -> 16 distinct banks.

#define THREADS 256
#define ROWS_PER_BLOCK 1024
#define F4_PER_BLOCK (ROWS_PER_BLOCK * 7 / 4)   // 1792
#define OUT4_PER_BLOCK (ROWS_PER_BLOCK * 2)     // 2048

__global__ void __launch_bounds__(THREADS)
cbf_kernel(const float4* __restrict__ x4, float4* __restrict__ out4, int n)
{
    __shared__ float buf[ROWS_PER_BLOCK * 7];   // 28 KB

    const int tid = threadIdx.x;
    const int rowBase = blockIdx.x * ROWS_PER_BLOCK;
    const int rowsHere = min(ROWS_PER_BLOCK, n - rowBase);
    const int f4Here = (rowsHere * 7 + 3) >> 2;

    const long long f4Base  = (long long)blockIdx.x * F4_PER_BLOCK;
    const long long outBase = (long long)blockIdx.x * OUT4_PER_BLOCK;

    // Phase 1: coalesced float4 stage into shared (minimal load wavefronts).
    float4* bufv = (float4*)buf;
    #pragma unroll
    for (int k = 0; k < 7; k++) {
        int idx = k * THREADS + tid;
        if (idx < f4Here) bufv[idx] = x4[f4Base + idx];
    }
    __syncthreads();

    // Phase 2: contiguous sweep over output float4s (minimal store wavefronts).
    #pragma unroll
    for (int k = 0; k < 8; k++) {
        int idx = k * THREADS + tid;            // 0..2047 within block
        int row = idx >> 1;
        if (row < rowsHere) {
            float4 v;
            if (idx & 1) {
                v = make_float4(0.0f, 0.0f, 0.0f, 0.0f);
            } else {
                float x0 = buf[row * 7 + 0];
                float x1 = buf[row * 7 + 1];
                v = make_float4(1.0f + x0, 1.0f - x0, 1.0f + x1, 1.0f - x1);
            }
            out4[outBase + idx] = v;
        }
    }
}

extern "C" void kernel_launch(void* const* d_in, const int* in_sizes, int n_in,
                              void* d_out, int out_size)
{
    const float4* x4 = (const float4*)d_in[0];   // (B,7) fp32; B*7 divisible by 4
    float4* out4 = (float4*)d_out;               // (B,8) fp32 = 2 float4 per row

    const int n = in_sizes[0] / 7;               // B rows
    const int blocks = (n + ROWS_PER_BLOCK - 1) / ROWS_PER_BLOCK;
    cbf_kernel<<<blocks, THREADS>>>(x4, out4, n);
}